// round 16
// baseline (speedup 1.0000x reference)
#include <cuda_runtime.h>

#define Nn 50000
#define Rr 16
#define Hh 32
#define Ll 8
#define Ee 1600000
#define KT_BLOCKS 296
#define NT 169            // nodes per k_T block: 296*169 = 50024 >= Nn

// Scratch (static __device__ arrays: allocation-free per harness rules)
__device__ __align__(16) int   g_cnt[Rr * Nn];       // per-(relation,dst) edge counts
__device__ __align__(16) float g_enorm[Ee];          // per-edge 1/deg_r(dst) (layer1 writes)
__device__ __align__(16) float g_h1[Nn * Hh];        // layer-1 aggregation
__device__ __align__(16) float g_T[Nn * Rr * Ll];    // T[n][r][l] = (h1[n,:] @ W2[r])[l]

// Vector reduction: 4x fp32 add in one L2 atomic op (sm_90+)
__device__ __forceinline__ void red_add_v4(float* p, float4 v) {
    asm volatile("red.global.add.v4.f32 [%0], {%1,%2,%3,%4};"
                 :: "l"(p), "f"(v.x), "f"(v.y), "f"(v.z), "f"(v.w)
                 : "memory");
}

// ---------------------------------------------------------------------------
// Per-(relation,dst) edge counts. 8 edges per thread (MLP=8).
// ---------------------------------------------------------------------------
__global__ void k_count(const int* __restrict__ et, const int* __restrict__ dst) {
    int t = blockIdx.x * blockDim.x + threadIdx.x;
    if (t >= Ee / 8) return;
    int e0 = t * 8;
    int4 da = *(const int4*)(dst + e0);
    int4 db = *(const int4*)(dst + e0 + 4);
    int4 ra = *(const int4*)(et + e0);
    int4 rb = *(const int4*)(et + e0 + 4);
    atomicAdd(&g_cnt[ra.x * Nn + da.x], 1);
    atomicAdd(&g_cnt[ra.y * Nn + da.y], 1);
    atomicAdd(&g_cnt[ra.z * Nn + da.z], 1);
    atomicAdd(&g_cnt[ra.w * Nn + da.w], 1);
    atomicAdd(&g_cnt[rb.x * Nn + db.x], 1);
    atomicAdd(&g_cnt[rb.y * Nn + db.y], 1);
    atomicAdd(&g_cnt[rb.z * Nn + db.z], 1);
    atomicAdd(&g_cnt[rb.w * Nn + db.w], 1);
}

// ---------------------------------------------------------------------------
// Layer 1: 8 threads per edge (quarter-row each), 8 edges per thread (MLP=8).
//   norm = 1/max(cnt[r*N+d],1)   (inline gather)
//   g_h1[dst, q*4..] += W1[r, src, q*4..] * norm
// Lane q==0 stores the 8 edge-norms to g_enorm for layer2 reuse.
// ---------------------------------------------------------------------------
__global__ void k_layer1(const int* __restrict__ src, const int* __restrict__ dst,
                         const int* __restrict__ et, const float* __restrict__ W1) {
    int g = blockIdx.x * blockDim.x + threadIdx.x;
    int grp = g >> 3;        // which edge-octet
    int q = g & 7;           // which quarter of the 32-wide row
    if (grp >= Ee / 8) return;
    int e0 = grp * 8;

    int4 sa = *(const int4*)(src + e0);
    int4 sb = *(const int4*)(src + e0 + 4);
    int4 d4a = *(const int4*)(dst + e0);
    int4 d4b = *(const int4*)(dst + e0 + 4);
    int4 r4a = *(const int4*)(et + e0);
    int4 r4b = *(const int4*)(et + e0 + 4);
    int ss[8] = {sa.x, sa.y, sa.z, sa.w, sb.x, sb.y, sb.z, sb.w};
    int dd[8] = {d4a.x, d4a.y, d4a.z, d4a.w, d4b.x, d4b.y, d4b.z, d4b.w};
    int rr[8] = {r4a.x, r4a.y, r4a.z, r4a.w, r4b.x, r4b.y, r4b.z, r4b.w};

    int cc[8];
#pragma unroll
    for (int k = 0; k < 8; k++) cc[k] = __ldg(&g_cnt[rr[k] * Nn + dd[k]]);

    float4 ww[8];
#pragma unroll
    for (int k = 0; k < 8; k++)
        ww[k] = *(const float4*)(W1 + (rr[k] * Nn + ss[k]) * Hh + q * 4);

    float nn[8];
#pragma unroll
    for (int k = 0; k < 8; k++) nn[k] = 1.0f / fmaxf((float)cc[k], 1.0f);

    if (q == 0) {
        *(float4*)(g_enorm + e0)     = make_float4(nn[0], nn[1], nn[2], nn[3]);
        *(float4*)(g_enorm + e0 + 4) = make_float4(nn[4], nn[5], nn[6], nn[7]);
    }
#pragma unroll
    for (int k = 0; k < 8; k++) {
        float4 v = make_float4(ww[k].x * nn[k], ww[k].y * nn[k],
                               ww[k].z * nn[k], ww[k].w * nn[k]);
        red_add_v4(&g_h1[dd[k] * Hh + q * 4], v);
    }
}

// ---------------------------------------------------------------------------
// Fused k_T (register-weight GEMM, single balanced wave, 2-node ILP):
//   h = relu(agg + root1 + b1)                (staged ~21.6KB shared per block)
//   T[n][r][l] = sum_h h[n,h] * W2[r,h,l]     (w column = 32 regs, via shared)
//   out[n,l]   = (h @ root2)[l] + b2[l]       (base for layer2 REDs)
// Grid = 296 = 2 blocks x 148 SMs, one balanced wave.
// Main loop processes TWO nodes per iteration: 16 independent LDS.128 then
// 8 independent FFMA chains -> ~2x exposed-latency reduction vs R15.
// ---------------------------------------------------------------------------
__global__ void __launch_bounds__(512, 2)
k_T(const float* __restrict__ W2, const float* __restrict__ root1,
    const float* __restrict__ b1, const float* __restrict__ root2,
    const float* __restrict__ b2, float* __restrict__ out) {
    __shared__ float4 sH[NT * 8];        // 169 nodes x 32 h = 21.6KB
    __shared__ float  sW2[Rr * Hh * Ll]; // 16KB
    __shared__ float  sR[Hh * Ll];       // 1KB

    int tid = threadIdx.x;
    int n0 = blockIdx.x * NT;            // first node of this block

    for (int i = tid; i < Rr * Hh * Ll; i += 512) sW2[i] = W2[i];
    for (int i = tid; i < Hh * Ll; i += 512) sR[i] = root2[i];

    // Stage relu(agg + root1 + b1) for NT nodes (coalesced float4 loads)
    int base4 = n0 * 8;                  // float4 index into [n][h] arrays
    for (int idx4 = tid; idx4 < NT * 8; idx4 += 512) {
        int g4 = base4 + idx4;
        float4 hv = make_float4(0.f, 0.f, 0.f, 0.f);
        if (g4 < (Nn * Hh) / 4) {
            float4 av = ((const float4*)g_h1)[g4];
            float4 rv = ((const float4*)root1)[g4];
            int h0 = (idx4 & 7) * 4;
            hv.x = fmaxf(av.x + rv.x + __ldg(b1 + h0 + 0), 0.0f);
            hv.y = fmaxf(av.y + rv.y + __ldg(b1 + h0 + 1), 0.0f);
            hv.z = fmaxf(av.z + rv.z + __ldg(b1 + h0 + 2), 0.0f);
            hv.w = fmaxf(av.w + rv.w + __ldg(b1 + h0 + 3), 0.0f);
        }
        sH[idx4] = hv;
    }
    __syncthreads();

    // W2 column into registers: thread owns (r, l); conflict-free LDS
    int rl = tid & 127;                  // r*8 + l
    int r  = rl >> 3;
    int l  = rl & 7;
    int grp = tid >> 7;                  // 4 node-groups
    float w[Hh];
#pragma unroll
    for (int hh = 0; hh < Hh; hh++)
        w[hh] = sW2[(r * Hh + hh) * Ll + l];

    // Out-base: NT*8 (node,l) tasks over 512 threads
    for (int task = tid; task < NT * 8; task += 512) {
        int node = task >> 3;
        int lo = task & 7;
        int n = n0 + node;
        if (n < Nn) {
            const float* sHf = (const float*)sH;
            float y = __ldg(b2 + lo);
#pragma unroll
            for (int hh = 0; hh < Hh; hh++)
                y += sHf[node * Hh + hh] * sR[hh * Ll + lo];
            out[n * Ll + lo] = y;
        }
    }

    // Main: group grp handles nodes ni = grp + 4i; 2 nodes per iteration.
    // 22 iterations cover i = 0..43 (niA = grp+8ii, niB = grp+8ii+4).
#pragma unroll 2
    for (int ii = 0; ii < 22; ii++) {
        int niA = grp + ii * 8;
        int niB = niA + 4;
        if (niA >= NT) break;
        int niBc = (niB < NT) ? niB : niA;           // clamp for safe LDS
        int nA = n0 + niA;
        int nB = n0 + niB;

        float a0 = 0.f, a1 = 0.f, a2 = 0.f, a3 = 0.f;
        float c0 = 0.f, c1 = 0.f, c2 = 0.f, c3 = 0.f;
#pragma unroll
        for (int j = 0; j < 8; j++) {
            float4 hA = sH[niA * 8 + j];             // broadcast LDS.128
            float4 hB = sH[niBc * 8 + j];            // independent of hA
            a0 += hA.x * w[j * 4 + 0];
            a1 += hA.y * w[j * 4 + 1];
            a2 += hA.z * w[j * 4 + 2];
            a3 += hA.w * w[j * 4 + 3];
            c0 += hB.x * w[j * 4 + 0];
            c1 += hB.y * w[j * 4 + 1];
            c2 += hB.z * w[j * 4 + 2];
            c3 += hB.w * w[j * 4 + 3];
        }
        if (nA < Nn)
            g_T[nA * (Rr * Ll) + rl] = (a0 + a1) + (a2 + a3);
        if (niB < NT && nB < Nn)
            g_T[nB * (Rr * Ll) + rl] = (c0 + c1) + (c2 + c3);
    }
}

// ---------------------------------------------------------------------------
// Layer 2 edge pass: 2 threads per edge (half-row each), 8 edges per thread.
//   out[dst, half*4..] += enorm[e] * T[src][r][half*4..]
// ---------------------------------------------------------------------------
__global__ void k_layer2(const int* __restrict__ src, const int* __restrict__ dst,
                         const int* __restrict__ et, float* __restrict__ out) {
    int g = blockIdx.x * blockDim.x + threadIdx.x;
    int oct = g >> 1;
    int half = g & 1;
    if (oct >= Ee / 8) return;
    int e0 = oct * 8;

    int4 sa = *(const int4*)(src + e0);
    int4 sb = *(const int4*)(src + e0 + 4);
    int4 da = *(const int4*)(dst + e0);
    int4 db = *(const int4*)(dst + e0 + 4);
    int4 ra = *(const int4*)(et + e0);
    int4 rb = *(const int4*)(et + e0 + 4);
    float4 na = *(const float4*)(g_enorm + e0);
    float4 nb = *(const float4*)(g_enorm + e0 + 4);
    int ss[8] = {sa.x, sa.y, sa.z, sa.w, sb.x, sb.y, sb.z, sb.w};
    int dd[8] = {da.x, da.y, da.z, da.w, db.x, db.y, db.z, db.w};
    int rr[8] = {ra.x, ra.y, ra.z, ra.w, rb.x, rb.y, rb.z, rb.w};
    float nn[8] = {na.x, na.y, na.z, na.w, nb.x, nb.y, nb.z, nb.w};

    float4 tv[8];
#pragma unroll
    for (int k = 0; k < 8; k++) {
        tv[k] = *(const float4*)(g_T + (ss[k] * Rr + rr[k]) * Ll + half * 4);
    }
#pragma unroll
    for (int k = 0; k < 8; k++) {
        float4 v = make_float4(tv[k].x * nn[k], tv[k].y * nn[k],
                               tv[k].z * nn[k], tv[k].w * nn[k]);
        red_add_v4(&out[dd[k] * Ll + half * 4], v);
    }
}

// ---------------------------------------------------------------------------
// Final: out = sigmoid(out), elementwise (MUFU exp)
// ---------------------------------------------------------------------------
__global__ void k_final(float* __restrict__ out) {
    int i = blockIdx.x * blockDim.x + threadIdx.x;
    if (i >= (Nn * Ll) / 4) return;
    float4 v = ((const float4*)out)[i];
    v.x = 1.0f / (1.0f + __expf(-v.x));
    v.y = 1.0f / (1.0f + __expf(-v.y));
    v.z = 1.0f / (1.0f + __expf(-v.z));
    v.w = 1.0f / (1.0f + __expf(-v.w));
    ((float4*)out)[i] = v;
}

// ---------------------------------------------------------------------------
extern "C" void kernel_launch(void* const* d_in, const int* in_sizes, int n_in,
                              void* d_out, int out_size) {
    const int* ei    = (const int*)d_in[0];    // edge_index [2, E]
    const int* et    = (const int*)d_in[1];    // edge_type  [E]
    const float* W1  = (const float*)d_in[2];  // [R, N, H]
    const float* rt1 = (const float*)d_in[3];  // [N, H]
    const float* b1  = (const float*)d_in[4];  // [H]
    const float* W2  = (const float*)d_in[5];  // [R, H, L]
    const float* rt2 = (const float*)d_in[6];  // [H, L]
    const float* b2  = (const float*)d_in[7];  // [L]
    float* out = (float*)d_out;                // [N, L]

    const int* src = ei;
    const int* dst = ei + Ee;

    // Zero accumulators via graph-capturable memset nodes (no alloc)
    void* cnt_ptr = nullptr;
    void* h1_ptr = nullptr;
    cudaGetSymbolAddress(&cnt_ptr, g_cnt);
    cudaGetSymbolAddress(&h1_ptr, g_h1);
    cudaMemsetAsync(cnt_ptr, 0, Rr * Nn * sizeof(int), 0);
    cudaMemsetAsync(h1_ptr, 0, Nn * Hh * sizeof(float), 0);

    k_count<<<(Ee / 8 + 255) / 256, 256>>>(et, dst);
    k_layer1<<<(Ee / 8) * 8 / 256, 256>>>(src, dst, et, W1);     // 8 thr/edge, 8 edges/thr
    k_T<<<KT_BLOCKS, 512>>>(W2, rt1, b1, rt2, b2, out);          // 1 balanced wave, 2-node ILP
    k_layer2<<<((Ee / 8) * 2 + 255) / 256, 256>>>(src, dst, et, out); // 2 thr/edge, 8 edges/thr
    k_final<<<((Nn * Ll) / 4 + 255) / 256, 256>>>(out);
}

// round 17
// speedup vs baseline: 1.0055x; 1.0055x over previous
#include <cuda_runtime.h>

#define Nn 50000
#define Rr 16
#define Hh 32
#define Ll 8
#define Ee 1600000
#define KT_BLOCKS 296
#define NT 169            // nodes per k_T block: 296*169 = 50024 >= Nn

// Scratch (static __device__ arrays: allocation-free per harness rules)
__device__ __align__(16) int   g_cnt[Rr * Nn];       // per-(relation,dst) edge counts
__device__ __align__(16) float g_enorm[Ee];          // per-edge 1/deg_r(dst) (layer1 writes)
__device__ __align__(16) float g_h1[Nn * Hh];        // layer-1 aggregation
__device__ __align__(16) float g_T[Nn * Rr * Ll];    // T[n][r][l] = (h1[n,:] @ W2[r])[l]

// Vector reduction: 4x fp32 add in one L2 atomic op (sm_90+)
__device__ __forceinline__ void red_add_v4(float* p, float4 v) {
    asm volatile("red.global.add.v4.f32 [%0], {%1,%2,%3,%4};"
                 :: "l"(p), "f"(v.x), "f"(v.y), "f"(v.z), "f"(v.w)
                 : "memory");
}

// ---------------------------------------------------------------------------
// Per-(relation,dst) edge counts. 8 edges per thread (MLP=8).
// ---------------------------------------------------------------------------
__global__ void k_count(const int* __restrict__ et, const int* __restrict__ dst) {
    int t = blockIdx.x * blockDim.x + threadIdx.x;
    if (t >= Ee / 8) return;
    int e0 = t * 8;
    int4 da = *(const int4*)(dst + e0);
    int4 db = *(const int4*)(dst + e0 + 4);
    int4 ra = *(const int4*)(et + e0);
    int4 rb = *(const int4*)(et + e0 + 4);
    atomicAdd(&g_cnt[ra.x * Nn + da.x], 1);
    atomicAdd(&g_cnt[ra.y * Nn + da.y], 1);
    atomicAdd(&g_cnt[ra.z * Nn + da.z], 1);
    atomicAdd(&g_cnt[ra.w * Nn + da.w], 1);
    atomicAdd(&g_cnt[rb.x * Nn + db.x], 1);
    atomicAdd(&g_cnt[rb.y * Nn + db.y], 1);
    atomicAdd(&g_cnt[rb.z * Nn + db.z], 1);
    atomicAdd(&g_cnt[rb.w * Nn + db.w], 1);
}

// ---------------------------------------------------------------------------
// Layer 1: 8 threads per edge (quarter-row each), 8 edges per thread (MLP=8).
//   norm = 1/max(cnt[r*N+d],1)   (inline gather)
//   g_h1[dst, q*4..] += W1[r, src, q*4..] * norm
// Lane q==0 stores the 8 edge-norms to g_enorm for layer2 reuse.
// ---------------------------------------------------------------------------
__global__ void k_layer1(const int* __restrict__ src, const int* __restrict__ dst,
                         const int* __restrict__ et, const float* __restrict__ W1) {
    int g = blockIdx.x * blockDim.x + threadIdx.x;
    int grp = g >> 3;        // which edge-octet
    int q = g & 7;           // which quarter of the 32-wide row
    if (grp >= Ee / 8) return;
    int e0 = grp * 8;

    int4 sa = *(const int4*)(src + e0);
    int4 sb = *(const int4*)(src + e0 + 4);
    int4 d4a = *(const int4*)(dst + e0);
    int4 d4b = *(const int4*)(dst + e0 + 4);
    int4 r4a = *(const int4*)(et + e0);
    int4 r4b = *(const int4*)(et + e0 + 4);
    int ss[8] = {sa.x, sa.y, sa.z, sa.w, sb.x, sb.y, sb.z, sb.w};
    int dd[8] = {d4a.x, d4a.y, d4a.z, d4a.w, d4b.x, d4b.y, d4b.z, d4b.w};
    int rr[8] = {r4a.x, r4a.y, r4a.z, r4a.w, r4b.x, r4b.y, r4b.z, r4b.w};

    int cc[8];
#pragma unroll
    for (int k = 0; k < 8; k++) cc[k] = __ldg(&g_cnt[rr[k] * Nn + dd[k]]);

    float4 ww[8];
#pragma unroll
    for (int k = 0; k < 8; k++)
        ww[k] = *(const float4*)(W1 + (rr[k] * Nn + ss[k]) * Hh + q * 4);

    float nn[8];
#pragma unroll
    for (int k = 0; k < 8; k++) nn[k] = 1.0f / fmaxf((float)cc[k], 1.0f);

    if (q == 0) {
        *(float4*)(g_enorm + e0)     = make_float4(nn[0], nn[1], nn[2], nn[3]);
        *(float4*)(g_enorm + e0 + 4) = make_float4(nn[4], nn[5], nn[6], nn[7]);
    }
#pragma unroll
    for (int k = 0; k < 8; k++) {
        float4 v = make_float4(ww[k].x * nn[k], ww[k].y * nn[k],
                               ww[k].z * nn[k], ww[k].w * nn[k]);
        red_add_v4(&g_h1[dd[k] * Hh + q * 4], v);
    }
}

// ---------------------------------------------------------------------------
// Fused k_T (register-weight GEMM, single balanced wave)  [R15-proven form]
//   h = relu(agg + root1 + b1)                (staged ~21.6KB shared per block)
//   T[n][r][l] = sum_h h[n,h] * W2[r,h,l]     (w column = 32 regs, via shared)
//   out[n,l]   = (h @ root2)[l] + b2[l]       (base for layer2 REDs)
// Grid = 296 = 2 blocks x 148 SMs, one balanced wave.
// ---------------------------------------------------------------------------
__global__ void __launch_bounds__(512, 2)
k_T(const float* __restrict__ W2, const float* __restrict__ root1,
    const float* __restrict__ b1, const float* __restrict__ root2,
    const float* __restrict__ b2, float* __restrict__ out) {
    __shared__ float4 sH[NT * 8];        // 169 nodes x 32 h = 21.6KB
    __shared__ float  sW2[Rr * Hh * Ll]; // 16KB
    __shared__ float  sR[Hh * Ll];       // 1KB

    int tid = threadIdx.x;
    int n0 = blockIdx.x * NT;            // first node of this block

    for (int i = tid; i < Rr * Hh * Ll; i += 512) sW2[i] = W2[i];
    for (int i = tid; i < Hh * Ll; i += 512) sR[i] = root2[i];

    // Stage relu(agg + root1 + b1) for NT nodes (coalesced float4 loads)
    int base4 = n0 * 8;                  // float4 index into [n][h] arrays
    for (int idx4 = tid; idx4 < NT * 8; idx4 += 512) {
        int g4 = base4 + idx4;
        float4 hv = make_float4(0.f, 0.f, 0.f, 0.f);
        if (g4 < (Nn * Hh) / 4) {
            float4 av = ((const float4*)g_h1)[g4];
            float4 rv = ((const float4*)root1)[g4];
            int h0 = (idx4 & 7) * 4;
            hv.x = fmaxf(av.x + rv.x + __ldg(b1 + h0 + 0), 0.0f);
            hv.y = fmaxf(av.y + rv.y + __ldg(b1 + h0 + 1), 0.0f);
            hv.z = fmaxf(av.z + rv.z + __ldg(b1 + h0 + 2), 0.0f);
            hv.w = fmaxf(av.w + rv.w + __ldg(b1 + h0 + 3), 0.0f);
        }
        sH[idx4] = hv;
    }
    __syncthreads();

    // W2 column into registers: thread owns (r, l); conflict-free LDS
    int rl = tid & 127;                  // r*8 + l
    int r  = rl >> 3;
    int l  = rl & 7;
    int grp = tid >> 7;                  // 4 node-groups
    float w[Hh];
#pragma unroll
    for (int hh = 0; hh < Hh; hh++)
        w[hh] = sW2[(r * Hh + hh) * Ll + l];

    // Out-base: NT*8 (node,l) tasks over 512 threads
    for (int task = tid; task < NT * 8; task += 512) {
        int node = task >> 3;
        int lo = task & 7;
        int n = n0 + node;
        if (n < Nn) {
            const float* sHf = (const float*)sH;
            float y = __ldg(b2 + lo);
#pragma unroll
            for (int hh = 0; hh < Hh; hh++)
                y += sHf[node * Hh + hh] * sR[hh * Ll + lo];
            out[n * Ll + lo] = y;
        }
    }

    // Main: group grp handles nodes ni = grp, grp+4, ... (43 per group)
#pragma unroll 4
    for (int i = 0; i < 43; i++) {
        int ni = grp + i * 4;
        if (ni >= NT) break;
        int n = n0 + ni;
        if (n >= Nn) break;
        float a0 = 0.0f, a1 = 0.0f, a2 = 0.0f, a3 = 0.0f;
#pragma unroll
        for (int j = 0; j < 8; j++) {
            float4 h4 = sH[ni * 8 + j];          // broadcast LDS.128
            a0 += h4.x * w[j * 4 + 0];
            a1 += h4.y * w[j * 4 + 1];
            a2 += h4.z * w[j * 4 + 2];
            a3 += h4.w * w[j * 4 + 3];
        }
        g_T[n * (Rr * Ll) + rl] = (a0 + a1) + (a2 + a3);
    }
}

// ---------------------------------------------------------------------------
// Layer 2 edge pass: 2 threads per edge (half-row each), 4 edges per thread.
// Lower per-thread state (~32 regs) + 2x thread count vs R16 -> more resident
// warps to hide the scattered T-gather latency (issue was 7.5%).
//   out[dst, half*4..] += enorm[e] * T[src][r][half*4..]
// ---------------------------------------------------------------------------
__global__ void k_layer2(const int* __restrict__ src, const int* __restrict__ dst,
                         const int* __restrict__ et, float* __restrict__ out) {
    int g = blockIdx.x * blockDim.x + threadIdx.x;
    int quad = g >> 1;
    int half = g & 1;
    if (quad >= Ee / 4) return;
    int e0 = quad * 4;

    int4 s4 = *(const int4*)(src + e0);
    int4 d4 = *(const int4*)(dst + e0);
    int4 r4 = *(const int4*)(et + e0);
    float4 n4 = *(const float4*)(g_enorm + e0);
    int ss[4] = {s4.x, s4.y, s4.z, s4.w};
    int dd[4] = {d4.x, d4.y, d4.z, d4.w};
    int rr[4] = {r4.x, r4.y, r4.z, r4.w};
    float nn[4] = {n4.x, n4.y, n4.z, n4.w};

    float4 tv[4];
#pragma unroll
    for (int k = 0; k < 4; k++) {
        tv[k] = *(const float4*)(g_T + (ss[k] * Rr + rr[k]) * Ll + half * 4);
    }
#pragma unroll
    for (int k = 0; k < 4; k++) {
        float4 v = make_float4(tv[k].x * nn[k], tv[k].y * nn[k],
                               tv[k].z * nn[k], tv[k].w * nn[k]);
        red_add_v4(&out[dd[k] * Ll + half * 4], v);
    }
}

// ---------------------------------------------------------------------------
// Final: out = sigmoid(out), elementwise (MUFU exp)
// ---------------------------------------------------------------------------
__global__ void k_final(float* __restrict__ out) {
    int i = blockIdx.x * blockDim.x + threadIdx.x;
    if (i >= (Nn * Ll) / 4) return;
    float4 v = ((const float4*)out)[i];
    v.x = 1.0f / (1.0f + __expf(-v.x));
    v.y = 1.0f / (1.0f + __expf(-v.y));
    v.z = 1.0f / (1.0f + __expf(-v.z));
    v.w = 1.0f / (1.0f + __expf(-v.w));
    ((float4*)out)[i] = v;
}

// ---------------------------------------------------------------------------
extern "C" void kernel_launch(void* const* d_in, const int* in_sizes, int n_in,
                              void* d_out, int out_size) {
    const int* ei    = (const int*)d_in[0];    // edge_index [2, E]
    const int* et    = (const int*)d_in[1];    // edge_type  [E]
    const float* W1  = (const float*)d_in[2];  // [R, N, H]
    const float* rt1 = (const float*)d_in[3];  // [N, H]
    const float* b1  = (const float*)d_in[4];  // [H]
    const float* W2  = (const float*)d_in[5];  // [R, H, L]
    const float* rt2 = (const float*)d_in[6];  // [H, L]
    const float* b2  = (const float*)d_in[7];  // [L]
    float* out = (float*)d_out;                // [N, L]

    const int* src = ei;
    const int* dst = ei + Ee;

    // Zero accumulators via graph-capturable memset nodes (no alloc)
    void* cnt_ptr = nullptr;
    void* h1_ptr = nullptr;
    cudaGetSymbolAddress(&cnt_ptr, g_cnt);
    cudaGetSymbolAddress(&h1_ptr, g_h1);
    cudaMemsetAsync(cnt_ptr, 0, Rr * Nn * sizeof(int), 0);
    cudaMemsetAsync(h1_ptr, 0, Nn * Hh * sizeof(float), 0);

    k_count<<<(Ee / 8 + 255) / 256, 256>>>(et, dst);
    k_layer1<<<(Ee / 8) * 8 / 256, 256>>>(src, dst, et, W1);     // 8 thr/edge, 8 edges/thr
    k_T<<<KT_BLOCKS, 512>>>(W2, rt1, b1, rt2, b2, out);          // 1 balanced wave
    k_layer2<<<((Ee / 4) * 2 + 255) / 256, 256>>>(src, dst, et, out); // 2 thr/edge, 4 edges/thr
    k_final<<<((Nn * Ll) / 4 + 255) / 256, 256>>>(out);
}